// round 14
// baseline (speedup 1.0000x reference)
#include <cuda_runtime.h>
#include <cstdint>

// PSRoIPool, single fused kernel: per-(plane,batch) block does
//   (a) compact+decode batch-b rois into smem (only this block's i/j bounds),
//   (b) stage plane (LDG.128 -> STS.128, padded float4 layout),
//   (c) float4 row-prefix scan (short carry chain),
//   (d) table-driven gather: window sum = sum_rows R[hy][we-1]-R[hy][ws-1].
// x (4, 1029, 96, 96) fp32, rois (512,5) fp32, out (512, 21, 7, 7) fp32.
//
// NUMERIC CONTRACT (verified R5): bin sizes are reciprocal-multiplies
// __fmul_rn(extent, fl(1/7)) — NOT divisions. Do not change.

#define C_TOT   1029
#define PH      7
#define PW      7
#define HH      96
#define WW      96
#define W4      24            // float4s per row
#define WP4     25            // padded float4 row stride (100 floats)
#define WPF     (WP4*4)
#define PLANE   (HH*WW)
#define KROIS   512
#define NBATCH  4
#define SCALE   0.0625f
#define RCP7    0.1428571492433547973632812500f   // fl(1/7) = 0x3E124925
#define THREADS 256

__global__ __launch_bounds__(THREADS) void psroi_fused(
    const float* __restrict__ x,
    const float* __restrict__ rois,
    float* __restrict__ out)
{
    __shared__ float4   sp4[HH * WP4];     // 38400 B prefix-sum plane
    __shared__ int      s_kk [KROIS];      // compacted roi ids (batch b)
    __shared__ uint32_t s_bnd[KROIS];      // hs | he<<8 | ws<<16 | we<<24
    __shared__ int      s_cnt;
    float* const sp = (float*)sp4;

    const int p   = blockIdx.x;            // plane/channel 0..1028
    const int b   = blockIdx.y;            // batch 0..3
    const int ij  = p % (PH * PW);
    const int i   = ij / PW;
    const int j   = ij - i * PW;
    const int tid = threadIdx.x;

    if (tid == 0) s_cnt = 0;
    __syncthreads();

    // ---- (a) Compact + decode rois of batch b (2 rois per thread).
    #pragma unroll
    for (int t = 0; t < 2; ++t) {
        const int k = tid + t * THREADS;
        const float* roi = rois + k * 5;
        if ((int)__ldg(roi) != b) continue;
        const int sw = (int)floorf(__fmaf_rn(__ldg(roi + 1), SCALE, 0.5f));
        const int sh = (int)floorf(__fmaf_rn(__ldg(roi + 2), SCALE, 0.5f));
        const int ew = (int)floorf(__fmaf_rn(__ldg(roi + 3), SCALE, 0.5f));
        const int eh = (int)floorf(__fmaf_rn(__ldg(roi + 4), SCALE, 0.5f));
        const float bin_h = __fmul_rn((float)max(eh - sh, 1), RCP7);
        const float bin_w = __fmul_rn((float)max(ew - sw, 1), RCP7);
        const int hs = min(max((int)floorf(__fmul_rn((float)i,       bin_h)) + sh, 0), HH);
        const int he = min(max((int)ceilf (__fmul_rn((float)(i + 1), bin_h)) + sh, 0), HH);
        const int ws = min(max((int)floorf(__fmul_rn((float)j,       bin_w)) + sw, 0), WW);
        const int we = min(max((int)ceilf (__fmul_rn((float)(j + 1), bin_w)) + sw, 0), WW);
        const int slot = atomicAdd(&s_cnt, 1);
        s_kk [slot] = k;
        s_bnd[slot] = (uint32_t)hs | ((uint32_t)he << 8)
                    | ((uint32_t)ws << 16) | ((uint32_t)we << 24);
    }

    // ---- (b) Stage plane (b,p): coalesced LDG.128 -> STS.128.
    const float4* __restrict__ src4 =
        (const float4*)(x + ((size_t)b * C_TOT + p) * PLANE);
    #pragma unroll
    for (int q = 0; q < PLANE / 4 / THREADS; ++q) {      // 9
        const int e   = tid + q * THREADS;
        const int row = e / W4;
        const int c4  = e - row * W4;
        sp4[row * WP4 + c4] = __ldg(src4 + e);
    }
    __syncthreads();

    // ---- (c) Row prefix (float4 pipeline, short carry chain).
    if (tid < HH) {
        float4* __restrict__ rr = sp4 + tid * WP4;
        float run = 0.0f;
        #pragma unroll
        for (int q = 0; q < W4; ++q) {
            float4 v = rr[q];
            const float s01 = v.x + v.y;
            const float s4  = s01 + (v.z + v.w);
            float4 o;
            o.x = run + v.x;
            o.y = run + s01;
            o.z = o.y + v.z;
            o.w = run + s4;
            rr[q] = o;
            run   = o.w;
        }
    }
    __syncthreads();

    // ---- (d) Gather: all lanes active, no decode math.
    const int cnt = s_cnt;
    for (int n = tid; n < cnt; n += THREADS) {
        const uint32_t bnd = s_bnd[n];
        const int hs = bnd & 0xff;
        const int he = (bnd >> 8) & 0xff;
        const int ws = (bnd >> 16) & 0xff;
        const int we = bnd >> 24;
        const int kk = s_kk[n];

        const int area = (he - hs) * (we - ws);
        float val = 0.0f;
        if (area > 0) {
            float acc = 0.0f;
            const float* __restrict__ right = sp + (we - 1);
            if (ws > 0) {
                const float* __restrict__ left = sp + (ws - 1);
                for (int hy = hs; hy < he; ++hy)
                    acc += right[hy * WPF] - left[hy * WPF];
            } else {
                for (int hy = hs; hy < he; ++hy)
                    acc += right[hy * WPF];
            }
            val = __fdiv_rn(acc, (float)area);
        }
        out[kk * C_TOT + p] = val;
    }
}

extern "C" void kernel_launch(void* const* d_in, const int* in_sizes, int n_in,
                              void* d_out, int out_size)
{
    const float* x;
    const float* rois;
    if (n_in >= 2 && in_sizes[0] == KROIS * 5) {
        rois = (const float*)d_in[0];
        x    = (const float*)d_in[1];
    } else {
        x    = (const float*)d_in[0];
        rois = (const float*)d_in[1];
    }
    float* out = (float*)d_out;

    dim3 grid(C_TOT, NBATCH);
    psroi_fused<<<grid, THREADS>>>(x, rois, out);
}